// round 16
// baseline (speedup 1.0000x reference)
#include <cuda_runtime.h>
#include <math.h>
#include <stdint.h>

#define CHI 64
#define CHO 64
#define HH 128
#define WW 128
#define BB 4
#define HW (HH*WW)          /* 16384 pixels per plane */
#define NPIX (BB*HW)        /* 65536 pixels total */

// Scratch buffers (static device globals; no allocation anywhere)
__device__ float g_y[BB*CHO*HW];      // pre-BN deform-conv output
__device__ float g_part[64*256*2];    // BN partials: [ch][cta] sums, then squares

// ======== tf32 mma.sync primitives (sm_80+ PTX; valid at target sm_103) =====
__device__ __forceinline__ uint32_t f2tf32(float v) {
    uint32_t r;
    asm("cvt.rna.tf32.f32 %0, %1;" : "=r"(r) : "f"(v));
    return r;
}
__device__ __forceinline__ void mma_tf32(float* d, const uint32_t* a,
                                         const uint32_t* b) {
    asm volatile(
        "mma.sync.aligned.m16n8k8.row.col.f32.tf32.tf32.f32 "
        "{%0,%1,%2,%3}, {%4,%5,%6,%7}, {%8,%9}, {%0,%1,%2,%3};"
        : "+f"(d[0]), "+f"(d[1]), "+f"(d[2]), "+f"(d[3])
        : "r"(a[0]), "r"(a[1]), "r"(a[2]), "r"(a[3]), "r"(b[0]), "r"(b[1]));
}

// ======== deform tap: folds bilinear weights, validity, sigmoid mask ========
// Offsets now come from SMEM (off_s, pitch FOPAD) instead of global memory.
struct Tap {
    float w00, w01, w10, w11;
    int   i00, i01, i10, i11;
};

#define FOPAD 264

__device__ __forceinline__ Tap make_tap_s(const float* off_s, int kk,
                                          int tid, int h, int wx) {
    Tap t;
    const float dy = off_s[(2*kk  )*FOPAD + tid];
    const float dx = off_s[(2*kk+1)*FOPAD + tid];
    const float ml = off_s[(18+kk)*FOPAD + tid];
    const float mask = 1.f / (1.f + __expf(-ml));
    const int ky = kk / 3;
    const int kx = kk - ky*3;
    const float py = (float)(h  - 1 + ky) + dy;
    const float px = (float)(wx - 1 + kx) + dx;
    const float fy0 = floorf(py);
    const float fx0 = floorf(px);
    const float wy  = py - fy0;
    const float wxf = px - fx0;
    const int iy0 = (int)fy0;
    const int ix0 = (int)fx0;
    const int iy1 = iy0 + 1;
    const int ix1 = ix0 + 1;
    const float vy0 = (iy0 >= 0 && iy0 < HH) ? 1.f : 0.f;
    const float vy1 = (iy1 >= 0 && iy1 < HH) ? 1.f : 0.f;
    const float vx0 = (ix0 >= 0 && ix0 < WW) ? 1.f : 0.f;
    const float vx1 = (ix1 >= 0 && ix1 < WW) ? 1.f : 0.f;
    const int cy0 = min(max(iy0, 0), HH-1);
    const int cy1 = min(max(iy1, 0), HH-1);
    const int cx0 = min(max(ix0, 0), WW-1);
    const int cx1 = min(max(ix1, 0), WW-1);
    t.w00 = (1.f-wy)*(1.f-wxf)*vy0*vx0*mask;
    t.w01 = (1.f-wy)*wxf      *vy0*vx1*mask;
    t.w10 = wy      *(1.f-wxf)*vy1*vx0*mask;
    t.w11 = wy      *wxf      *vy1*vx1*mask;
    t.i00 = cy0*WW + cx0;
    t.i01 = cy0*WW + cx1;
    t.i10 = cy1*WW + cx0;
    t.i11 = cy1*WW + cx1;
    return t;
}

// ===========================================================================
// Kernel 1: FUSED offset conv + deformable conv, tf32 mma.sync.
// Grid NPIX/256, block 256, 2 CTAs/SM.
// Phase 1: offset conv (M=256 px, N=32/27 used, K=9*64) -> off_s in SMEM.
// Phase 2: deform gather (taps from off_s) + contraction (N=64) -> g_y,
//          with fused BN stage-1 partials.
// SMEM: Vt[64][264] | Ws[64][68] | off_s[27][264]  = 113,504 B per CTA.
// ===========================================================================
#define FVPAD 264
#define FWPAD 68
#define F_WS  (64*FVPAD)
#define F_OFF (F_WS + 64*FWPAD)
#define FSMEM ((64*FVPAD + 64*FWPAD + 27*FOPAD) * 4)

__global__ __launch_bounds__(256, 2)
void fused_dcn_kernel(const float* __restrict__ x,
                      const float* __restrict__ w_off,
                      const float* __restrict__ b_off,
                      const float* __restrict__ w,
                      const float* __restrict__ bias) {
    extern __shared__ uint32_t sm[];
    uint32_t* Vt    = sm;                   // [64][FVPAD]
    uint32_t* Ws    = sm + F_WS;            // [64][FWPAD] (phase 1 uses 32 rows)
    float*    off_s = (float*)(sm + F_OFF); // [27][FOPAD]

    const int tid  = threadIdx.x;
    const int warp = tid >> 5;
    const int lane = tid & 31;
    const int gr   = lane >> 2;
    const int gc   = lane & 3;
    const int m0   = warp << 5;

    const int blk     = blockIdx.x;
    const int b       = blk >> 6;
    const int remBase = (blk & 63) << 8;
    const int rem     = remBase + tid;
    const int h       = rem >> 7;
    const int wx      = rem & 127;
    const float* xb   = x + b*(CHI*HW);

    // ---------------- Phase 1: offset conv -> off_s ----------------
    {
        float acc[2][4][4];
        #pragma unroll
        for (int mt = 0; mt < 2; mt++)
            #pragma unroll
            for (int n = 0; n < 4; n++)
                #pragma unroll
                for (int q = 0; q < 4; q++)
                    acc[mt][n][q] = 0.f;

        for (int kk = 0; kk < 9; kk++) {
            const int ky = kk / 3;
            const int kx = kk - ky*3;

            #pragma unroll
            for (int j = 0; j < 8; j++) {
                const int i = tid + (j << 8);
                const int o = i >> 6;
                const int c = i & 63;
                Ws[o*FWPAD + c] = (o < 27) ? f2tf32(w_off[o*576 + c*9 + kk]) : 0u;
            }
            {
                const int yy = h + ky - 1;
                const int xx = wx + kx - 1;
                const bool ok = (yy >= 0 && yy < HH && xx >= 0 && xx < WW);
                const float* xp = xb + (ok ? yy*WW + xx : 0);
                #pragma unroll 8
                for (int c = 0; c < 64; c++)
                    Vt[c*FVPAD + tid] = f2tf32(ok ? xp[c*HW] : 0.f);
            }
            __syncthreads();

            #pragma unroll
            for (int kc = 0; kc < 8; kc++) {
                const int k0 = kc << 3;
                uint32_t bf[4][2];
                #pragma unroll
                for (int n = 0; n < 4; n++) {
                    const int orow = (n << 3) + gr;
                    bf[n][0] = Ws[orow*FWPAD + k0 + gc];
                    bf[n][1] = Ws[orow*FWPAD + k0 + gc + 4];
                }
                uint32_t af[2][4];
                #pragma unroll
                for (int mt = 0; mt < 2; mt++) {
                    const int m = m0 + (mt << 4);
                    af[mt][0] = Vt[(k0 + gc    )*FVPAD + m + gr];
                    af[mt][1] = Vt[(k0 + gc    )*FVPAD + m + gr + 8];
                    af[mt][2] = Vt[(k0 + gc + 4)*FVPAD + m + gr];
                    af[mt][3] = Vt[(k0 + gc + 4)*FVPAD + m + gr + 8];
                }
                #pragma unroll
                for (int mt = 0; mt < 2; mt++)
                    #pragma unroll
                    for (int n = 0; n < 4; n++)
                        mma_tf32(acc[mt][n], af[mt], bf[n]);
            }
            __syncthreads();
        }

        // write 27 live channels (+ bias) into SMEM off_s [ch][px_local]
        const int o0 = gc << 1;
        #pragma unroll
        for (int mt = 0; mt < 2; mt++) {
            const int r0 = m0 + (mt << 4) + gr;    // local pixel index
            #pragma unroll
            for (int n = 0; n < 4; n++) {
                const int oa = (n << 3) + o0;
                if (oa < 27) {
                    const float bv = b_off[oa];
                    off_s[oa*FOPAD + r0    ] = acc[mt][n][0] + bv;
                    off_s[oa*FOPAD + r0 + 8] = acc[mt][n][2] + bv;
                }
                if (oa + 1 < 27) {
                    const float bv = b_off[oa+1];
                    off_s[(oa+1)*FOPAD + r0    ] = acc[mt][n][1] + bv;
                    off_s[(oa+1)*FOPAD + r0 + 8] = acc[mt][n][3] + bv;
                }
            }
        }
        __syncthreads();   // off_s complete before phase 2 reads it
    }

    // ---------------- Phase 2: deformable conv -> g_y + partials ----------
    float acc[2][8][4];
    #pragma unroll
    for (int mt = 0; mt < 2; mt++)
        #pragma unroll
        for (int n = 0; n < 8; n++)
            #pragma unroll
            for (int q = 0; q < 4; q++)
                acc[mt][n][q] = 0.f;

    for (int kk = 0; kk < 9; kk++) {
        #pragma unroll
        for (int j = 0; j < 16; j++) {
            const int i = tid + (j << 8);
            const int o = i >> 6;
            const int c = i & 63;
            Ws[o*FWPAD + c] = f2tf32(w[o*576 + c*9 + kk]);
        }
        {
            const Tap tp = make_tap_s(off_s, kk, tid, h, wx);
            const float* p00 = xb + tp.i00;
            const float* p01 = xb + tp.i01;
            const float* p10 = xb + tp.i10;
            const float* p11 = xb + tp.i11;
            #pragma unroll 8
            for (int c = 0; c < 64; c++) {
                const int off = c*HW;
                const float v = tp.w00*p00[off] + tp.w01*p01[off]
                              + tp.w10*p10[off] + tp.w11*p11[off];
                Vt[c*FVPAD + tid] = f2tf32(v);
            }
        }
        __syncthreads();

        #pragma unroll
        for (int kc = 0; kc < 8; kc++) {
            const int k0 = kc << 3;
            uint32_t bf[8][2];
            #pragma unroll
            for (int n = 0; n < 8; n++) {
                const int orow = (n << 3) + gr;
                bf[n][0] = Ws[orow*FWPAD + k0 + gc];
                bf[n][1] = Ws[orow*FWPAD + k0 + gc + 4];
            }
            uint32_t af[2][4];
            #pragma unroll
            for (int mt = 0; mt < 2; mt++) {
                const int m = m0 + (mt << 4);
                af[mt][0] = Vt[(k0 + gc    )*FVPAD + m + gr];
                af[mt][1] = Vt[(k0 + gc    )*FVPAD + m + gr + 8];
                af[mt][2] = Vt[(k0 + gc + 4)*FVPAD + m + gr];
                af[mt][3] = Vt[(k0 + gc + 4)*FVPAD + m + gr + 8];
            }
            #pragma unroll
            for (int mt = 0; mt < 2; mt++)
                #pragma unroll
                for (int n = 0; n < 8; n++)
                    mma_tf32(acc[mt][n], af[mt], bf[n]);
        }
        __syncthreads();
    }

    // Epilogue: y = acc + bias -> g_y, fused BN partials (as in R15).
    float* yb    = g_y + b*(CHO*HW);
    float* ws_s  = (float*)sm;         // reuse Vt region: [8][64]
    float* ws_ss = (float*)sm + 512;
    const int o0  = gc << 1;
    const int r0A = remBase + m0 + gr;
    const int r0B = r0A + 16;
    #pragma unroll
    for (int n = 0; n < 8; n++) {
        const int oa = (n << 3) + o0;
        const float b0 = bias[oa];
        const float b1 = bias[oa+1];
        const float y00 = acc[0][n][0] + b0;
        const float y01 = acc[0][n][1] + b1;
        const float y02 = acc[0][n][2] + b0;
        const float y03 = acc[0][n][3] + b1;
        const float y10 = acc[1][n][0] + b0;
        const float y11 = acc[1][n][1] + b1;
        const float y12 = acc[1][n][2] + b0;
        const float y13 = acc[1][n][3] + b1;
        yb[ oa   *HW + r0A    ] = y00;
        yb[(oa+1)*HW + r0A    ] = y01;
        yb[ oa   *HW + r0A + 8] = y02;
        yb[(oa+1)*HW + r0A + 8] = y03;
        yb[ oa   *HW + r0B    ] = y10;
        yb[(oa+1)*HW + r0B    ] = y11;
        yb[ oa   *HW + r0B + 8] = y12;
        yb[(oa+1)*HW + r0B + 8] = y13;

        float s0  = y00 + y02 + y10 + y12;
        float ss0 = y00*y00 + y02*y02 + y10*y10 + y12*y12;
        float s1  = y01 + y03 + y11 + y13;
        float ss1 = y01*y01 + y03*y03 + y11*y11 + y13*y13;
        s0  += __shfl_xor_sync(0xffffffffu, s0, 4);
        s0  += __shfl_xor_sync(0xffffffffu, s0, 8);
        s0  += __shfl_xor_sync(0xffffffffu, s0, 16);
        ss0 += __shfl_xor_sync(0xffffffffu, ss0, 4);
        ss0 += __shfl_xor_sync(0xffffffffu, ss0, 8);
        ss0 += __shfl_xor_sync(0xffffffffu, ss0, 16);
        s1  += __shfl_xor_sync(0xffffffffu, s1, 4);
        s1  += __shfl_xor_sync(0xffffffffu, s1, 8);
        s1  += __shfl_xor_sync(0xffffffffu, s1, 16);
        ss1 += __shfl_xor_sync(0xffffffffu, ss1, 4);
        ss1 += __shfl_xor_sync(0xffffffffu, ss1, 8);
        ss1 += __shfl_xor_sync(0xffffffffu, ss1, 16);
        if (lane < 4) {
            ws_s [warp*64 + oa    ] = s0;
            ws_s [warp*64 + oa + 1] = s1;
            ws_ss[warp*64 + oa    ] = ss0;
            ws_ss[warp*64 + oa + 1] = ss1;
        }
    }
    __syncthreads();
    if (tid < 64) {
        float s = 0.f, q = 0.f;
        #pragma unroll
        for (int wg = 0; wg < 8; wg++) {
            s += ws_s [wg*64 + tid];
            q += ws_ss[wg*64 + tid];
        }
        g_part[tid*256 + blockIdx.x]         = s;
        g_part[16384 + tid*256 + blockIdx.x] = q;
    }
}

// ===========================================================================
// Kernel 2: per-channel stats finalize + normalize + ReLU -> d_out.
// Grid 64 channels x 16 slices. Each block tree-reduces its channel's 256
// CTA partials (deterministic, identical across a channel's 16 blocks),
// then streams its 4096-element slice.
// ===========================================================================
__global__ __launch_bounds__(256)
void norm_kernel(float4* __restrict__ out,
                 const float* __restrict__ gamma,
                 const float* __restrict__ beta) {
    const int ch    = blockIdx.x >> 4;
    const int slice = blockIdx.x & 15;
    const int tid   = threadIdx.x;

    __shared__ float sh_s[256], sh_ss[256];
    __shared__ float sh_scale, sh_shift;
    sh_s[tid]  = g_part[ch*256 + tid];
    sh_ss[tid] = g_part[16384 + ch*256 + tid];
    __syncthreads();
    for (int st = 128; st > 0; st >>= 1) {
        if (tid < st) { sh_s[tid] += sh_s[tid+st]; sh_ss[tid] += sh_ss[tid+st]; }
        __syncthreads();
    }
    if (tid == 0) {
        const float inv  = 1.f / (float)NPIX;
        const float mean = sh_s[0] * inv;
        const float var  = sh_ss[0] * inv - mean*mean;
        const float rstd = rsqrtf(var + 1e-5f);
        const float sc   = rstd * gamma[ch];
        sh_scale = sc;
        sh_shift = beta[ch] - mean*sc;
    }
    __syncthreads();
    const float sc = sh_scale;
    const float sh = sh_shift;

    // stream this channel's slice: 1024 float4 per slice, 4 per thread
    #pragma unroll
    for (int k = 0; k < 4; k++) {
        const int j  = slice*1024 + k*256 + tid;   // float4 idx within channel
        const int bb = j >> 12;                    // 4096 float4 per (b, ch) plane
        const int q4 = j & 4095;
        const int i  = bb*(CHO*HW/4) + ch*(HW/4) + q4;
        float4 v = ((const float4*)g_y)[i];
        v.x = fmaxf(v.x*sc + sh, 0.f);
        v.y = fmaxf(v.y*sc + sh, 0.f);
        v.z = fmaxf(v.z*sc + sh, 0.f);
        v.w = fmaxf(v.w*sc + sh, 0.f);
        out[i] = v;
    }
}

extern "C" void kernel_launch(void* const* d_in, const int* in_sizes, int n_in,
                              void* d_out, int out_size) {
    const float* x     = (const float*)d_in[0];
    const float* w_off = (const float*)d_in[1];
    const float* b_off = (const float*)d_in[2];
    const float* w     = (const float*)d_in[3];
    const float* b     = (const float*)d_in[4];
    const float* gamma = (const float*)d_in[5];
    const float* beta  = (const float*)d_in[6];

    cudaFuncSetAttribute(fused_dcn_kernel,
                         cudaFuncAttributeMaxDynamicSharedMemorySize, FSMEM);

    fused_dcn_kernel<<<NPIX/256, 256, FSMEM>>>(x, w_off, b_off, w, b);
    norm_kernel<<<64*16, 256>>>((float4*)d_out, gamma, beta);
}

// round 17
// speedup vs baseline: 1.1270x; 1.1270x over previous
#include <cuda_runtime.h>
#include <math.h>
#include <stdint.h>

#define CHI 64
#define CHO 64
#define HH 128
#define WW 128
#define BB 4
#define HW (HH*WW)          /* 16384 pixels per plane */
#define NPIX (BB*HW)        /* 65536 pixels total */

// Scratch buffers (static device globals; no allocation anywhere)
__device__ float g_off[BB*27*HW];     // offset-conv output, 27 channels
__device__ float g_y[BB*CHO*HW];      // pre-BN deform-conv output
__device__ float g_part[64*256*2];    // BN partials: [ch][cta] sums, then squares

// ======== tf32 mma.sync primitives (sm_80+ PTX; valid at target sm_103) =====
__device__ __forceinline__ uint32_t f2tf32(float v) {
    uint32_t r;
    asm("cvt.rna.tf32.f32 %0, %1;" : "=r"(r) : "f"(v));
    return r;
}
__device__ __forceinline__ void mma_tf32(float* d, const uint32_t* a,
                                         const uint32_t* b) {
    asm volatile(
        "mma.sync.aligned.m16n8k8.row.col.f32.tf32.tf32.f32 "
        "{%0,%1,%2,%3}, {%4,%5,%6,%7}, {%8,%9}, {%0,%1,%2,%3};"
        : "+f"(d[0]), "+f"(d[1]), "+f"(d[2]), "+f"(d[3])
        : "r"(a[0]), "r"(a[1]), "r"(a[2]), "r"(a[3]), "r"(b[0]), "r"(b[1]));
}

// ======== deform tap: folds bilinear weights, validity, sigmoid mask ========
struct Tap {
    float w00, w01, w10, w11;
    int   i00, i01, i10, i11;
};

__device__ __forceinline__ Tap make_tap(const float* offb, int kk, int h, int wx) {
    Tap t;
    const float dy = offb[(2*kk  )*HW];
    const float dx = offb[(2*kk+1)*HW];
    const float ml = offb[(18+kk)*HW];
    const float mask = 1.f / (1.f + __expf(-ml));
    const int ky = kk / 3;
    const int kx = kk - ky*3;
    const float py = (float)(h  - 1 + ky) + dy;
    const float px = (float)(wx - 1 + kx) + dx;
    const float fy0 = floorf(py);
    const float fx0 = floorf(px);
    const float wy  = py - fy0;
    const float wxf = px - fx0;
    const int iy0 = (int)fy0;
    const int ix0 = (int)fx0;
    const int iy1 = iy0 + 1;
    const int ix1 = ix0 + 1;
    const float vy0 = (iy0 >= 0 && iy0 < HH) ? 1.f : 0.f;
    const float vy1 = (iy1 >= 0 && iy1 < HH) ? 1.f : 0.f;
    const float vx0 = (ix0 >= 0 && ix0 < WW) ? 1.f : 0.f;
    const float vx1 = (ix1 >= 0 && ix1 < WW) ? 1.f : 0.f;
    const int cy0 = min(max(iy0, 0), HH-1);
    const int cy1 = min(max(iy1, 0), HH-1);
    const int cx0 = min(max(ix0, 0), WW-1);
    const int cx1 = min(max(ix1, 0), WW-1);
    t.w00 = (1.f-wy)*(1.f-wxf)*vy0*vx0*mask;
    t.w01 = (1.f-wy)*wxf      *vy0*vx1*mask;
    t.w10 = wy      *(1.f-wxf)*vy1*vx0*mask;
    t.w11 = wy      *wxf      *vy1*vx1*mask;
    t.i00 = cy0*WW + cx0;
    t.i01 = cy0*WW + cx1;
    t.i10 = cy1*WW + cx0;
    t.i11 = cy1*WW + cx1;
    return t;
}

// ===========================================================================
// Kernel A: offset conv (64 -> 27 ch, 3x3, pad 1) via tf32 mma.sync.
// Grid NPIX/256, block 256, 2 CTAs/SM.
// ===========================================================================
#define OVPAD 264
#define OWPAD 68
#define OW_OFF (64*OVPAD)
#define OSMEM ((64*OVPAD + 32*OWPAD) * 4)   /* 76288 bytes */

__global__ __launch_bounds__(256, 2)
void offset_mma_kernel(const float* __restrict__ x,
                       const float* __restrict__ w_off,
                       const float* __restrict__ b_off) {
    extern __shared__ uint32_t sm[];
    uint32_t* Vt = sm;            // [64][OVPAD]
    uint32_t* Ws = sm + OW_OFF;   // [32][OWPAD]

    const int tid  = threadIdx.x;
    const int warp = tid >> 5;
    const int lane = tid & 31;
    const int gr   = lane >> 2;
    const int gc   = lane & 3;
    const int m0   = warp << 5;

    const int blk     = blockIdx.x;
    const int b       = blk >> 6;
    const int remBase = (blk & 63) << 8;
    const int rem     = remBase + tid;
    const int h       = rem >> 7;
    const int wx      = rem & 127;
    const float* xb   = x + b*(CHI*HW);

    float acc[2][4][4];
    #pragma unroll
    for (int mt = 0; mt < 2; mt++)
        #pragma unroll
        for (int n = 0; n < 4; n++)
            #pragma unroll
            for (int q = 0; q < 4; q++)
                acc[mt][n][q] = 0.f;

    for (int kk = 0; kk < 9; kk++) {
        const int ky = kk / 3;
        const int kx = kk - ky*3;

        #pragma unroll
        for (int j = 0; j < 8; j++) {
            const int i = tid + (j << 8);
            const int o = i >> 6;
            const int c = i & 63;
            Ws[o*OWPAD + c] = (o < 27) ? f2tf32(w_off[o*576 + c*9 + kk]) : 0u;
        }
        {
            const int yy = h + ky - 1;
            const int xx = wx + kx - 1;
            const bool ok = (yy >= 0 && yy < HH && xx >= 0 && xx < WW);
            const float* xp = xb + (ok ? yy*WW + xx : 0);
            #pragma unroll 8
            for (int c = 0; c < 64; c++)
                Vt[c*OVPAD + tid] = f2tf32(ok ? xp[c*HW] : 0.f);
        }
        __syncthreads();

        #pragma unroll
        for (int kc = 0; kc < 8; kc++) {
            const int k0 = kc << 3;
            uint32_t bf[4][2];
            #pragma unroll
            for (int n = 0; n < 4; n++) {
                const int orow = (n << 3) + gr;
                bf[n][0] = Ws[orow*OWPAD + k0 + gc];
                bf[n][1] = Ws[orow*OWPAD + k0 + gc + 4];
            }
            uint32_t af[2][4];
            #pragma unroll
            for (int mt = 0; mt < 2; mt++) {
                const int m = m0 + (mt << 4);
                af[mt][0] = Vt[(k0 + gc    )*OVPAD + m + gr];
                af[mt][1] = Vt[(k0 + gc    )*OVPAD + m + gr + 8];
                af[mt][2] = Vt[(k0 + gc + 4)*OVPAD + m + gr];
                af[mt][3] = Vt[(k0 + gc + 4)*OVPAD + m + gr + 8];
            }
            #pragma unroll
            for (int mt = 0; mt < 2; mt++)
                #pragma unroll
                for (int n = 0; n < 4; n++)
                    mma_tf32(acc[mt][n], af[mt], bf[n]);
        }
        __syncthreads();
    }

    float* ob = g_off + b*(27*HW);
    const int o0 = gc << 1;
    #pragma unroll
    for (int mt = 0; mt < 2; mt++) {
        const int r0 = remBase + m0 + (mt << 4) + gr;
        #pragma unroll
        for (int n = 0; n < 4; n++) {
            const int oa = (n << 3) + o0;
            if (oa < 27) {
                const float bv = b_off[oa];
                ob[oa*HW + r0    ] = acc[mt][n][0] + bv;
                ob[oa*HW + r0 + 8] = acc[mt][n][2] + bv;
            }
            if (oa + 1 < 27) {
                const float bv = b_off[oa+1];
                ob[(oa+1)*HW + r0    ] = acc[mt][n][1] + bv;
                ob[(oa+1)*HW + r0 + 8] = acc[mt][n][3] + bv;
            }
        }
    }
}

// ===========================================================================
// Kernel B: deformable gather + tf32 mma.sync contraction, with fused BN
// stage-1 partials (R15 version — measured 2 CTAs/SM config).
// ===========================================================================
#define VPAD 264
#define WPAD 68
#define W_OFF (64*VPAD)
#define DSMEM ((64*VPAD + 64*WPAD) * 4)   /* 84992 bytes */

__global__ __launch_bounds__(256, 2)
void deform_mma_kernel(const float* __restrict__ x,
                       const float* __restrict__ w,
                       const float* __restrict__ bias) {
    extern __shared__ uint32_t sm[];
    uint32_t* Vt = sm;           // [64][VPAD]
    uint32_t* Ws = sm + W_OFF;   // [64][WPAD]

    const int tid  = threadIdx.x;
    const int warp = tid >> 5;
    const int lane = tid & 31;
    const int gr   = lane >> 2;
    const int gc   = lane & 3;
    const int m0   = warp << 5;

    const int p    = blockIdx.x * 256 + tid;
    const int b    = p >> 14;
    const int rem  = p & 16383;
    const int h    = rem >> 7;
    const int wx   = rem & 127;
    const int remBase = (int)(blockIdx.x & 63) << 8;

    const float* xb   = x + b*(CHI*HW);
    const float* offb = g_off + b*(27*HW) + rem;

    float acc[2][8][4];
    #pragma unroll
    for (int mt = 0; mt < 2; mt++)
        #pragma unroll
        for (int n = 0; n < 8; n++)
            #pragma unroll
            for (int q = 0; q < 4; q++)
                acc[mt][n][q] = 0.f;

    for (int kk = 0; kk < 9; kk++) {
        #pragma unroll
        for (int j = 0; j < 16; j++) {
            const int i = tid + (j << 8);
            const int o = i >> 6;
            const int c = i & 63;
            Ws[o*WPAD + c] = f2tf32(w[o*576 + c*9 + kk]);
        }
        {
            const Tap tp = make_tap(offb, kk, h, wx);
            const float* p00 = xb + tp.i00;
            const float* p01 = xb + tp.i01;
            const float* p10 = xb + tp.i10;
            const float* p11 = xb + tp.i11;
            #pragma unroll 8
            for (int c = 0; c < 64; c++) {
                const int off = c*HW;
                const float v = tp.w00*p00[off] + tp.w01*p01[off]
                              + tp.w10*p10[off] + tp.w11*p11[off];
                Vt[c*VPAD + tid] = f2tf32(v);
            }
        }
        __syncthreads();

        #pragma unroll
        for (int kc = 0; kc < 8; kc++) {
            const int k0 = kc << 3;
            uint32_t bf[8][2];
            #pragma unroll
            for (int n = 0; n < 8; n++) {
                const int orow = (n << 3) + gr;
                bf[n][0] = Ws[orow*WPAD + k0 + gc];
                bf[n][1] = Ws[orow*WPAD + k0 + gc + 4];
            }
            uint32_t af[2][4];
            #pragma unroll
            for (int mt = 0; mt < 2; mt++) {
                const int m = m0 + (mt << 4);
                af[mt][0] = Vt[(k0 + gc    )*VPAD + m + gr];
                af[mt][1] = Vt[(k0 + gc    )*VPAD + m + gr + 8];
                af[mt][2] = Vt[(k0 + gc + 4)*VPAD + m + gr];
                af[mt][3] = Vt[(k0 + gc + 4)*VPAD + m + gr + 8];
            }
            #pragma unroll
            for (int mt = 0; mt < 2; mt++)
                #pragma unroll
                for (int n = 0; n < 8; n++)
                    mma_tf32(acc[mt][n], af[mt], bf[n]);
        }
        __syncthreads();   // last iteration: barrier before SMEM reuse below
    }

    // Epilogue: y = acc + bias -> g_y, fused BN partials.
    float* yb    = g_y + b*(CHO*HW);
    float* ws_s  = (float*)sm;         // reuse Vt region: [8][64]
    float* ws_ss = (float*)sm + 512;
    const int o0  = gc << 1;
    const int r0A = remBase + m0 + gr;
    const int r0B = r0A + 16;
    #pragma unroll
    for (int n = 0; n < 8; n++) {
        const int oa = (n << 3) + o0;
        const float b0 = bias[oa];
        const float b1 = bias[oa+1];
        const float y00 = acc[0][n][0] + b0;
        const float y01 = acc[0][n][1] + b1;
        const float y02 = acc[0][n][2] + b0;
        const float y03 = acc[0][n][3] + b1;
        const float y10 = acc[1][n][0] + b0;
        const float y11 = acc[1][n][1] + b1;
        const float y12 = acc[1][n][2] + b0;
        const float y13 = acc[1][n][3] + b1;
        yb[ oa   *HW + r0A    ] = y00;
        yb[(oa+1)*HW + r0A    ] = y01;
        yb[ oa   *HW + r0A + 8] = y02;
        yb[(oa+1)*HW + r0A + 8] = y03;
        yb[ oa   *HW + r0B    ] = y10;
        yb[(oa+1)*HW + r0B    ] = y11;
        yb[ oa   *HW + r0B + 8] = y12;
        yb[(oa+1)*HW + r0B + 8] = y13;

        float s0  = y00 + y02 + y10 + y12;
        float ss0 = y00*y00 + y02*y02 + y10*y10 + y12*y12;
        float s1  = y01 + y03 + y11 + y13;
        float ss1 = y01*y01 + y03*y03 + y11*y11 + y13*y13;
        s0  += __shfl_xor_sync(0xffffffffu, s0, 4);
        s0  += __shfl_xor_sync(0xffffffffu, s0, 8);
        s0  += __shfl_xor_sync(0xffffffffu, s0, 16);
        ss0 += __shfl_xor_sync(0xffffffffu, ss0, 4);
        ss0 += __shfl_xor_sync(0xffffffffu, ss0, 8);
        ss0 += __shfl_xor_sync(0xffffffffu, ss0, 16);
        s1  += __shfl_xor_sync(0xffffffffu, s1, 4);
        s1  += __shfl_xor_sync(0xffffffffu, s1, 8);
        s1  += __shfl_xor_sync(0xffffffffu, s1, 16);
        ss1 += __shfl_xor_sync(0xffffffffu, ss1, 4);
        ss1 += __shfl_xor_sync(0xffffffffu, ss1, 8);
        ss1 += __shfl_xor_sync(0xffffffffu, ss1, 16);
        if (lane < 4) {
            ws_s [warp*64 + oa    ] = s0;
            ws_s [warp*64 + oa + 1] = s1;
            ws_ss[warp*64 + oa    ] = ss0;
            ws_ss[warp*64 + oa + 1] = ss1;
        }
    }
    __syncthreads();
    if (tid < 64) {
        float s = 0.f, q = 0.f;
        #pragma unroll
        for (int wg = 0; wg < 8; wg++) {
            s += ws_s [wg*64 + tid];
            q += ws_ss[wg*64 + tid];
        }
        g_part[tid*256 + blockIdx.x]         = s;
        g_part[16384 + tid*256 + blockIdx.x] = q;
    }
}

// ===========================================================================
// Kernel C: per-channel stats finalize + normalize + ReLU -> d_out
// (R16 version — measured 9.86 us). Grid 64 channels x 16 slices.
// ===========================================================================
__global__ __launch_bounds__(256)
void norm_kernel(float4* __restrict__ out,
                 const float* __restrict__ gamma,
                 const float* __restrict__ beta) {
    const int ch    = blockIdx.x >> 4;
    const int slice = blockIdx.x & 15;
    const int tid   = threadIdx.x;

    __shared__ float sh_s[256], sh_ss[256];
    __shared__ float sh_scale, sh_shift;
    sh_s[tid]  = g_part[ch*256 + tid];
    sh_ss[tid] = g_part[16384 + ch*256 + tid];
    __syncthreads();
    for (int st = 128; st > 0; st >>= 1) {
        if (tid < st) { sh_s[tid] += sh_s[tid+st]; sh_ss[tid] += sh_ss[tid+st]; }
        __syncthreads();
    }
    if (tid == 0) {
        const float inv  = 1.f / (float)NPIX;
        const float mean = sh_s[0] * inv;
        const float var  = sh_ss[0] * inv - mean*mean;
        const float rstd = rsqrtf(var + 1e-5f);
        const float sc   = rstd * gamma[ch];
        sh_scale = sc;
        sh_shift = beta[ch] - mean*sc;
    }
    __syncthreads();
    const float sc = sh_scale;
    const float sh = sh_shift;

    #pragma unroll
    for (int k = 0; k < 4; k++) {
        const int j  = slice*1024 + k*256 + tid;   // float4 idx within channel
        const int bb = j >> 12;                    // 4096 float4 per (b, ch) plane
        const int q4 = j & 4095;
        const int i  = bb*(CHO*HW/4) + ch*(HW/4) + q4;
        float4 v = ((const float4*)g_y)[i];
        v.x = fmaxf(v.x*sc + sh, 0.f);
        v.y = fmaxf(v.y*sc + sh, 0.f);
        v.z = fmaxf(v.z*sc + sh, 0.f);
        v.w = fmaxf(v.w*sc + sh, 0.f);
        out[i] = v;
    }
}

extern "C" void kernel_launch(void* const* d_in, const int* in_sizes, int n_in,
                              void* d_out, int out_size) {
    const float* x     = (const float*)d_in[0];
    const float* w_off = (const float*)d_in[1];
    const float* b_off = (const float*)d_in[2];
    const float* w     = (const float*)d_in[3];
    const float* b     = (const float*)d_in[4];
    const float* gamma = (const float*)d_in[5];
    const float* beta  = (const float*)d_in[6];

    cudaFuncSetAttribute(offset_mma_kernel,
                         cudaFuncAttributeMaxDynamicSharedMemorySize, OSMEM);
    cudaFuncSetAttribute(deform_mma_kernel,
                         cudaFuncAttributeMaxDynamicSharedMemorySize, DSMEM);

    offset_mma_kernel<<<NPIX/256, 256, OSMEM>>>(x, w_off, b_off);
    deform_mma_kernel<<<NPIX/256, 256, DSMEM>>>(x, w, b);
    norm_kernel<<<64*16, 256>>>((float4*)d_out, gamma, beta);
}